// round 10
// baseline (speedup 1.0000x reference)
#include <cuda_runtime.h>

#define NS   128         // samples per ray
#define NH   64          // hidden units
#define RPB  4           // rays per block (one warp per ray)
#define THREADS 128

typedef unsigned long long u64;

__device__ __forceinline__ u64 ffma2(u64 a, u64 b, u64 c) {
    u64 d;
    asm("fma.rn.f32x2 %0, %1, %2, %3;" : "=l"(d) : "l"(a), "l"(b), "l"(c));
    return d;
}
__device__ __forceinline__ u64 pack2(float lo, float hi) {
    u64 r;
    asm("mov.b64 %0, {%1, %2};" : "=l"(r) : "f"(lo), "f"(hi));
    return r;
}
__device__ __forceinline__ u64 relu2(u64 x) {
    float lo, hi;
    asm("mov.b64 {%0, %1}, %2;" : "=f"(lo), "=f"(hi) : "l"(x));
    lo = fmaxf(lo, 0.0f);
    hi = fmaxf(hi, 0.0f);
    return pack2(lo, hi);
}
__device__ __forceinline__ float sum2(u64 x) {   // lo + hi
    float lo, hi;
    asm("mov.b64 {%0, %1}, %2;" : "=f"(lo), "=f"(hi) : "l"(x));
    return lo + hi;
}
__device__ __forceinline__ float tanh_fast(float x) {
    float y;
    asm("tanh.approx.f32 %0, %1;" : "=f"(y) : "f"(x));
    return y;
}
// sigmoid(x) = 0.5*tanh(0.5x) + 0.5
__device__ __forceinline__ float sigmoid_fast(float x) {
    return fmaf(0.5f, tanh_fast(0.5f * x), 0.5f);
}

union F4U { float4 f; u64 q[2]; };

// One half-pass: MLP + activations for TWO samples (z packed as {z,z}).
// Returns alpha, v, rgb for both samples; accumulators die inside.
__device__ __forceinline__ void mlp_pass(
    const float4* __restrict__ sB, const float4* __restrict__ sS,
    const float4* __restrict__ sWS, const float4* __restrict__ sU0,
    const float4* __restrict__ sU1, const float4* __restrict__ sU2,
    u64 z0, u64 z1, float delta,
    float& alpha0, float& alpha1, float& v0, float& v1,
    float& r0, float& r1, float& g0, float& g1, float& b0, float& b1)
{
    u64 as0=0, as1=0, ar0=0, ar1=0, ag0=0, ag1=0, ab0=0, ab1=0;

    #pragma unroll 4
    for (int u = 0; u < NH/4; ++u) {
        F4U bs, sl, ws, q0, q1, q2;
        bs.f = sB[u];  sl.f = sS[u];  ws.f = sWS[u];
        q0.f = sU0[u]; q1.f = sU1[u]; q2.f = sU2[u];
        #pragma unroll
        for (int h = 0; h < 2; ++h) {        // two unit-pairs per float4
            const u64 B = bs.q[h], S = sl.q[h];
            const u64 h0 = relu2(ffma2(z0, S, B));
            const u64 h1 = relu2(ffma2(z1, S, B));
            as0 = ffma2(h0, ws.q[h], as0);  as1 = ffma2(h1, ws.q[h], as1);
            ar0 = ffma2(h0, q0.q[h], ar0);  ar1 = ffma2(h1, q0.q[h], ar1);
            ag0 = ffma2(h0, q1.q[h], ag0);  ag1 = ffma2(h1, q1.q[h], ag1);
            ab0 = ffma2(h0, q2.q[h], ab0);  ab1 = ffma2(h1, q2.q[h], ab1);
        }
    }

    // softplus in log2 domain (finite, branch-free):
    //   t = log2(1+e^s) = max(s,0)*log2e + log2(1 + e^(-|s|))
    //   alpha = 1 - exp2(-delta*t);  no 0*inf when delta==0 (miss rays).
    const float LOG2E = 1.4426950408889634f;
    {
        const float s = sum2(as0);
        const float t = fmaxf(s, 0.0f) * LOG2E + __log2f(1.0f + __expf(-fabsf(s)));
        alpha0 = 1.0f - exp2f(-delta * t);
        v0     = (1.0f - alpha0) + 1e-15f;
        r0 = sigmoid_fast(sum2(ar0));
        g0 = sigmoid_fast(sum2(ag0));
        b0 = sigmoid_fast(sum2(ab0));
    }
    {
        const float s = sum2(as1);
        const float t = fmaxf(s, 0.0f) * LOG2E + __log2f(1.0f + __expf(-fabsf(s)));
        alpha1 = 1.0f - exp2f(-delta * t);
        v1     = (1.0f - alpha1) + 1e-15f;
        r1 = sigmoid_fast(sum2(ar1));
        g1 = sigmoid_fast(sum2(ag1));
        b1 = sigmoid_fast(sum2(ab1));
    }
}

__global__ __launch_bounds__(THREADS, 8)
void nerf_render_kernel(
    const float* __restrict__ rays_o, const float* __restrict__ rays_d,
    const float* __restrict__ W1, const float* __restrict__ W2,
    const float* __restrict__ b1, const float* __restrict__ w_sigma,
    const float* __restrict__ W_color,
    float* __restrict__ out_image, float* __restrict__ out_depth,
    float* __restrict__ out_weights, float* __restrict__ out_wsum,
    const int BN)
{
    __shared__ float4 sWS4[NH/4];           // w_sigma
    __shared__ float4 sU04[NH/4];           // W_color[:,0]
    __shared__ float4 sU14[NH/4];           // W_color[:,1]
    __shared__ float4 sU24[NH/4];           // W_color[:,2]
    __shared__ float4 sBase4[RPB][NH/4];    // per-ray: o·W1 + d·W2 + b1
    __shared__ float4 sSlope4[RPB][NH/4];   // per-ray: d·W1

    const int tid  = threadIdx.x;
    const int lane = tid & 31;
    const int wid  = tid >> 5;
    const int r    = blockIdx.x * RPB + wid;
    const bool active = (r < BN);

    // ---- stage ray-independent weights, one unit per thread<64 ----
    if (tid < NH) {
        ((float*)sWS4)[tid] = w_sigma[tid];
        ((float*)sU04)[tid] = W_color[tid*3+0];
        ((float*)sU14)[tid] = W_color[tid*3+1];
        ((float*)sU24)[tid] = W_color[tid*3+2];
    }

    // ---- per-ray data (all lanes of a warp share one ray) ----
    float ox=0.f, oy=0.f, oz=0.f, dx=1.f, dy=1.f, dz=1.f;
    if (active) {
        ox = rays_o[r*3+0]; oy = rays_o[r*3+1]; oz = rays_o[r*3+2];
        dx = rays_d[r*3+0]; dy = rays_d[r*3+1]; dz = rays_d[r*3+2];
    }

    // ---- per-ray base/slope per hidden unit (2 units per lane) ----
    {
        float* bp = (float*)sBase4[wid];
        float* sp = (float*)sSlope4[wid];
        #pragma unroll
        for (int j = lane; j < NH; j += 32) {
            const float a0 = W1[j], a1 = W1[NH+j], a2 = W1[2*NH+j];
            sp[j] = dx*a0 + dy*a1 + dz*a2;
            bp[j] = ox*a0 + oy*a1 + oz*a2
                  + b1[j] + dx*W2[j] + dy*W2[NH+j] + dz*W2[2*NH+j];
        }
    }
    __syncthreads();

    // ---- near/far via cube AABB (replicates reference exactly) ----
    float near_t, far_t;
    {
        const float ivx = 1.0f/(dx + 1e-15f);
        const float ivy = 1.0f/(dy + 1e-15f);
        const float ivz = 1.0f/(dz + 1e-15f);
        const float t1x = (-1.0f - ox)*ivx, t2x = (1.0f - ox)*ivx;
        const float t1y = (-1.0f - oy)*ivy, t2y = (1.0f - oy)*ivy;
        const float t1z = (-1.0f - oz)*ivz, t2z = (1.0f - oz)*ivz;
        near_t = fmaxf(fmaxf(fminf(t1x,t2x), fminf(t1y,t2y)), fminf(t1z,t2z));
        far_t  = fminf(fminf(fmaxf(t1x,t2x), fmaxf(t1y,t2y)), fmaxf(t1z,t2z));
        if (far_t < near_t) { near_t = 1e9f; far_t = 1e9f; }   // miss
        near_t = fmaxf(near_t, 0.05f);                          // MIN_NEAR
    }
    const float span  = far_t - near_t;
    const float delta = span * (1.0f/(NS-1));

    const float4* sB = sBase4[wid];
    const float4* sS = sSlope4[wid];

    // ---- samples s = 4*lane + k; two half-passes of 2 samples each ----
    float alpha[4], v[4], rr[4], rg[4], rb[4];
    {
        const float z0 = near_t + span * ((float)(4*lane+0) * (1.0f/(NS-1)));
        const float z1 = near_t + span * ((float)(4*lane+1) * (1.0f/(NS-1)));
        mlp_pass(sB, sS, sWS4, sU04, sU14, sU24,
                 pack2(z0, z0), pack2(z1, z1), delta,
                 alpha[0], alpha[1], v[0], v[1],
                 rr[0], rr[1], rg[0], rg[1], rb[0], rb[1]);
    }
    {
        const float z2 = near_t + span * ((float)(4*lane+2) * (1.0f/(NS-1)));
        const float z3 = near_t + span * ((float)(4*lane+3) * (1.0f/(NS-1)));
        mlp_pass(sB, sS, sWS4, sU04, sU14, sU24,
                 pack2(z2, z2), pack2(z3, z3), delta,
                 alpha[2], alpha[3], v[2], v[3],
                 rr[2], rr[3], rg[2], rg[3], rb[2], rb[3]);
    }

    // ---- exclusive multiplicative scan over 128 samples (warp-local) ----
    const float l0 = v[0];
    const float l1 = l0 * v[1];
    const float l2 = l1 * v[2];
    const float l3 = l2 * v[3];
    float p = l3;
    #pragma unroll
    for (int off = 1; off < 32; off <<= 1) {
        const float n = __shfl_up_sync(0xffffffffu, p, off);
        if (lane >= off) p *= n;
    }
    float excl = __shfl_up_sync(0xffffffffu, p, 1);
    if (lane == 0) excl = 1.0f;
    float wt[4];
    wt[0] = alpha[0] * excl;
    wt[1] = alpha[1] * (excl * l0);
    wt[2] = alpha[2] * (excl * l1);
    wt[3] = alpha[3] * (excl * l2);

    // ---- outputs ----
    if (active) {
        float4 wv = make_float4(wt[0], wt[1], wt[2], wt[3]);
        *(float4*)(out_weights + (size_t)r * NS + 4*lane) = wv;
    }

    float s0 = 0.f, s1 = 0.f, s2 = 0.f, s3 = 0.f, s4 = 0.f;
    #pragma unroll
    for (int k = 0; k < 4; ++k) {
        const float zk = near_t + span * ((float)(4*lane+k) * (1.0f/(NS-1)));
        s0 += wt[k];
        s1 += wt[k] * zk;
        s2 += wt[k] * rr[k];
        s3 += wt[k] * rg[k];
        s4 += wt[k] * rb[k];
    }
    #pragma unroll
    for (int off = 16; off; off >>= 1) {
        s0 += __shfl_xor_sync(0xffffffffu, s0, off);
        s1 += __shfl_xor_sync(0xffffffffu, s1, off);
        s2 += __shfl_xor_sync(0xffffffffu, s2, off);
        s3 += __shfl_xor_sync(0xffffffffu, s3, off);
        s4 += __shfl_xor_sync(0xffffffffu, s4, off);
    }
    if (active && lane == 0) {
        out_wsum[r]      = s0;
        out_depth[r]     = s1;
        out_image[r*3+0] = s2;
        out_image[r*3+1] = s3;
        out_image[r*3+2] = s4;
    }
}

extern "C" void kernel_launch(void* const* d_in, const int* in_sizes, int n_in,
                              void* d_out, int out_size) {
    const float* rays_o  = (const float*)d_in[0];
    const float* rays_d  = (const float*)d_in[1];
    const float* W1      = (const float*)d_in[2];
    const float* W2      = (const float*)d_in[3];
    const float* b1      = (const float*)d_in[4];
    const float* w_sigma = (const float*)d_in[5];
    const float* W_color = (const float*)d_in[6];

    const int BN = in_sizes[0] / 3;   // B*N rays

    float* out = (float*)d_out;
    // output layout: image [BN,3], depth [BN], weights [BN,NS], weights_sum [BN]
    float* out_image   = out;
    float* out_depth   = out + (size_t)BN * 3;
    float* out_weights = out + (size_t)BN * 4;
    float* out_wsum    = out + (size_t)BN * 4 + (size_t)BN * NS;

    const int blocks = (BN + RPB - 1) / RPB;
    nerf_render_kernel<<<blocks, THREADS>>>(rays_o, rays_d, W1, W2, b1, w_sigma,
                                            W_color, out_image, out_depth,
                                            out_weights, out_wsum, BN);
}

// round 11
// speedup vs baseline: 1.1505x; 1.1505x over previous
#include <cuda_runtime.h>

#define NS   128         // samples per ray
#define NH   64          // hidden units
#define RPB  4           // rays per block (one warp per ray)
#define THREADS 128

typedef unsigned long long u64;

__device__ __forceinline__ u64 ffma2(u64 a, u64 b, u64 c) {
    u64 d;
    asm("fma.rn.f32x2 %0, %1, %2, %3;" : "=l"(d) : "l"(a), "l"(b), "l"(c));
    return d;
}
__device__ __forceinline__ u64 pack2(float lo, float hi) {
    u64 r;
    asm("mov.b64 %0, {%1, %2};" : "=l"(r) : "f"(lo), "f"(hi));
    return r;
}
__device__ __forceinline__ u64 relu2(u64 x) {
    float lo, hi;
    asm("mov.b64 {%0, %1}, %2;" : "=f"(lo), "=f"(hi) : "l"(x));
    lo = fmaxf(lo, 0.0f);
    hi = fmaxf(hi, 0.0f);
    return pack2(lo, hi);
}
__device__ __forceinline__ float sum2(u64 x) {   // lo + hi
    float lo, hi;
    asm("mov.b64 {%0, %1}, %2;" : "=f"(lo), "=f"(hi) : "l"(x));
    return lo + hi;
}
__device__ __forceinline__ float tanh_fast(float x) {
    float y;
    asm("tanh.approx.f32 %0, %1;" : "=f"(y) : "f"(x));
    return y;
}
// sigmoid(x) = 0.5*tanh(0.5x) + 0.5
__device__ __forceinline__ float sigmoid_fast(float x) {
    return fmaf(0.5f, tanh_fast(0.5f * x), 0.5f);
}

union F4U { float4 f; u64 q[2]; };

// Ray-independent output weights, transposed: warp-uniform -> constant bank
// so the inner-loop loads take the LDCU/uniform-register path (frees the
// smem crossbar AND reduces FFMA2 RF-bank pressure).
struct CW {
    float4 ws[NH/4];   // w_sigma
    float4 u0[NH/4];   // W_color[:,0]
    float4 u1[NH/4];   // W_color[:,1]
    float4 u2[NH/4];   // W_color[:,2]
};
__constant__ CW cW;
__device__   CW gScratch;

__global__ void repack_kernel(const float* __restrict__ w_sigma,
                              const float* __restrict__ W_color) {
    const int t = threadIdx.x;
    if (t < NH) {
        ((float*)gScratch.ws)[t] = w_sigma[t];
        ((float*)gScratch.u0)[t] = W_color[t*3+0];
        ((float*)gScratch.u1)[t] = W_color[t*3+1];
        ((float*)gScratch.u2)[t] = W_color[t*3+2];
    }
}

__global__ __launch_bounds__(THREADS)
void nerf_render_kernel(
    const float* __restrict__ rays_o, const float* __restrict__ rays_d,
    const float* __restrict__ W1, const float* __restrict__ W2,
    const float* __restrict__ b1,
    float* __restrict__ out_image, float* __restrict__ out_depth,
    float* __restrict__ out_weights, float* __restrict__ out_wsum,
    const int BN)
{
    __shared__ float4 sBase4[RPB][NH/4];    // per-ray: o·W1 + d·W2 + b1
    __shared__ float4 sSlope4[RPB][NH/4];   // per-ray: d·W1

    const int tid  = threadIdx.x;
    const int lane = tid & 31;
    const int wid  = tid >> 5;
    const int r    = blockIdx.x * RPB + wid;
    const bool active = (r < BN);

    // ---- per-ray data (all lanes of a warp share one ray) ----
    float ox=0.f, oy=0.f, oz=0.f, dx=1.f, dy=1.f, dz=1.f;
    if (active) {
        ox = rays_o[r*3+0]; oy = rays_o[r*3+1]; oz = rays_o[r*3+2];
        dx = rays_d[r*3+0]; dy = rays_d[r*3+1]; dz = rays_d[r*3+2];
    }

    // ---- per-ray base/slope per hidden unit (2 units per lane) ----
    {
        float* bp = (float*)sBase4[wid];
        float* sp = (float*)sSlope4[wid];
        #pragma unroll
        for (int j = lane; j < NH; j += 32) {
            const float a0 = W1[j], a1 = W1[NH+j], a2 = W1[2*NH+j];
            sp[j] = dx*a0 + dy*a1 + dz*a2;
            bp[j] = ox*a0 + oy*a1 + oz*a2
                  + b1[j] + dx*W2[j] + dy*W2[NH+j] + dz*W2[2*NH+j];
        }
    }
    __syncwarp();

    // ---- near/far via cube AABB (replicates reference exactly) ----
    float near_t, far_t;
    {
        const float ivx = 1.0f/(dx + 1e-15f);
        const float ivy = 1.0f/(dy + 1e-15f);
        const float ivz = 1.0f/(dz + 1e-15f);
        const float t1x = (-1.0f - ox)*ivx, t2x = (1.0f - ox)*ivx;
        const float t1y = (-1.0f - oy)*ivy, t2y = (1.0f - oy)*ivy;
        const float t1z = (-1.0f - oz)*ivz, t2z = (1.0f - oz)*ivz;
        near_t = fmaxf(fmaxf(fminf(t1x,t2x), fminf(t1y,t2y)), fminf(t1z,t2z));
        far_t  = fminf(fminf(fmaxf(t1x,t2x), fmaxf(t1y,t2y)), fmaxf(t1z,t2z));
        if (far_t < near_t) { near_t = 1e9f; far_t = 1e9f; }   // miss
        near_t = fmaxf(near_t, 0.05f);                          // MIN_NEAR
    }
    const float span  = far_t - near_t;
    const float delta = span * (1.0f/(NS-1));

    // ---- 4 contiguous samples per lane: s = 4*lane + k ----
    float zv[4];
    u64 zz[4];                 // {z,z} per sample (registers)
    #pragma unroll
    for (int k = 0; k < 4; ++k) {
        const int s = 4*lane + k;
        zv[k] = near_t + span * ((float)s * (1.0f/(NS-1)));
        zz[k] = pack2(zv[k], zv[k]);
    }

    // ---- MLP: pair-packed units, 4 units per iteration ----
    u64 as[4] = {0,0,0,0};     // sigma
    u64 ar[4] = {0,0,0,0};     // color r
    u64 ag[4] = {0,0,0,0};     // color g
    u64 ab[4] = {0,0,0,0};     // color b

    #pragma unroll 4
    for (int u = 0; u < NH/4; ++u) {
        F4U bs, sl, ws, q0, q1, q2;
        bs.f = sBase4[wid][u];
        sl.f = sSlope4[wid][u];
        ws.f = cW.ws[u];       // constant bank (uniform path)
        q0.f = cW.u0[u];
        q1.f = cW.u1[u];
        q2.f = cW.u2[u];
        #pragma unroll
        for (int h = 0; h < 2; ++h) {      // two unit-pairs per float4
            const u64 B = bs.q[h], S = sl.q[h];
            #pragma unroll
            for (int k = 0; k < 4; ++k) {
                const u64 hp = relu2(ffma2(zz[k], S, B));
                as[k] = ffma2(hp, ws.q[h], as[k]);
                ar[k] = ffma2(hp, q0.q[h], ar[k]);
                ag[k] = ffma2(hp, q1.q[h], ag[k]);
                ab[k] = ffma2(hp, q2.q[h], ab[k]);
            }
        }
    }

    // ---- activations + alpha per sample ----
    // softplus in log2 domain, branch-free and always FINITE:
    //   t = log2(1+e^s) = max(s,0)*log2e + log2(1 + e^(-|s|))
    //   alpha = 1 - exp2(-delta*t);  no 0*inf when delta==0 (miss rays).
    const float LOG2E = 1.4426950408889634f;
    float alpha[4], v[4], rr[4], rg[4], rb[4];
    #pragma unroll
    for (int k = 0; k < 4; ++k) {
        const float sacc = sum2(as[k]);
        const float en   = __expf(-fabsf(sacc));
        const float t    = fmaxf(sacc, 0.0f) * LOG2E + __log2f(1.0f + en);
        rr[k] = sigmoid_fast(sum2(ar[k]));
        rg[k] = sigmoid_fast(sum2(ag[k]));
        rb[k] = sigmoid_fast(sum2(ab[k]));
        alpha[k] = 1.0f - exp2f(-delta * t);
        v[k]     = (1.0f - alpha[k]) + 1e-15f;
    }

    // ---- exclusive multiplicative scan over 128 samples (warp-local) ----
    const float l0 = v[0];
    const float l1 = l0 * v[1];
    const float l2 = l1 * v[2];
    const float l3 = l2 * v[3];
    float p = l3;
    #pragma unroll
    for (int off = 1; off < 32; off <<= 1) {
        const float n = __shfl_up_sync(0xffffffffu, p, off);
        if (lane >= off) p *= n;
    }
    float excl = __shfl_up_sync(0xffffffffu, p, 1);
    if (lane == 0) excl = 1.0f;
    float wt[4];
    wt[0] = alpha[0] * excl;
    wt[1] = alpha[1] * (excl * l0);
    wt[2] = alpha[2] * (excl * l1);
    wt[3] = alpha[3] * (excl * l2);

    // ---- outputs ----
    if (active) {
        float4 wv = make_float4(wt[0], wt[1], wt[2], wt[3]);
        *(float4*)(out_weights + (size_t)r * NS + 4*lane) = wv;
    }

    float s0 = 0.f, s1 = 0.f, s2 = 0.f, s3 = 0.f, s4 = 0.f;
    #pragma unroll
    for (int k = 0; k < 4; ++k) {
        s0 += wt[k];
        s1 += wt[k] * zv[k];
        s2 += wt[k] * rr[k];
        s3 += wt[k] * rg[k];
        s4 += wt[k] * rb[k];
    }
    #pragma unroll
    for (int off = 16; off; off >>= 1) {
        s0 += __shfl_xor_sync(0xffffffffu, s0, off);
        s1 += __shfl_xor_sync(0xffffffffu, s1, off);
        s2 += __shfl_xor_sync(0xffffffffu, s2, off);
        s3 += __shfl_xor_sync(0xffffffffu, s3, off);
        s4 += __shfl_xor_sync(0xffffffffu, s4, off);
    }
    if (active && lane == 0) {
        out_wsum[r]      = s0;
        out_depth[r]     = s1;
        out_image[r*3+0] = s2;
        out_image[r*3+1] = s3;
        out_image[r*3+2] = s4;
    }
}

extern "C" void kernel_launch(void* const* d_in, const int* in_sizes, int n_in,
                              void* d_out, int out_size) {
    const float* rays_o  = (const float*)d_in[0];
    const float* rays_d  = (const float*)d_in[1];
    const float* W1      = (const float*)d_in[2];
    const float* W2      = (const float*)d_in[3];
    const float* b1      = (const float*)d_in[4];
    const float* w_sigma = (const float*)d_in[5];
    const float* W_color = (const float*)d_in[6];

    const int BN = in_sizes[0] / 3;   // B*N rays

    float* out = (float*)d_out;
    // output layout: image [BN,3], depth [BN], weights [BN,NS], weights_sum [BN]
    float* out_image   = out;
    float* out_depth   = out + (size_t)BN * 3;
    float* out_weights = out + (size_t)BN * 4;
    float* out_wsum    = out + (size_t)BN * 4 + (size_t)BN * NS;

    // 1) repack output weights into transposed layout in __device__ scratch
    repack_kernel<<<1, 64>>>(w_sigma, W_color);

    // 2) copy scratch -> __constant__ (D2D, graph-capturable, no allocation)
    void* scratch_ptr = nullptr;
    cudaGetSymbolAddress(&scratch_ptr, gScratch);
    cudaMemcpyToSymbolAsync(cW, scratch_ptr, sizeof(CW), 0,
                            cudaMemcpyDeviceToDevice, 0);

    // 3) main kernel
    const int blocks = (BN + RPB - 1) / RPB;
    nerf_render_kernel<<<blocks, THREADS>>>(rays_o, rays_d, W1, W2, b1,
                                            out_image, out_depth,
                                            out_weights, out_wsum, BN);
}